// round 15
// baseline (speedup 1.0000x reference)
#include <cuda_runtime.h>
#include <cuda_fp16.h>
#include <stdint.h>
#include <math.h>

#define MAXN 131072
#define PAD  8   // one float per 32B L2 sector for atomic targets

__device__ float  g_h[MAXN];            // x @ W                  [N]
__device__ float  g_dinv[MAXN];         // rsqrt(deg+1)           [N]
__device__ __half g_ph[MAXN];           // fp16 p = dinv*h        [N]
__device__ float  g_deg8[MAXN * PAD];   // sector-padded degree   (zeroed after use)
__device__ float  g_acc8[MAXN * PAD];   // sector-padded scatter  (zeroed after use)

// ---------------------------------------------------------------------------
// K1 (fused): per-warp row dot products, 2 rows/warp (ILP), streaming loads
// + grid-stride degree histogram into sector-padded bins (LTS atomics).
// ---------------------------------------------------------------------------
__global__ void k1_fused(const float* __restrict__ x,
                         const float* __restrict__ W,
                         const int*   __restrict__ dst,
                         int N, int C, int E) {
    int tid  = blockIdx.x * blockDim.x + threadIdx.x;
    int warp = tid >> 5;
    int lane = tid & 31;

    int r0 = warp * 2;
    int r1 = r0 + 1;

    if (r0 < N) {
        const float4* w4 = reinterpret_cast<const float4*>(W);
        float4 b0 = __ldg(&w4[lane]);
        float4 b1 = __ldg(&w4[lane + 32]);

        const float4* xr0 = reinterpret_cast<const float4*>(x + (size_t)r0 * C);
        float4 a0 = __ldcs(&xr0[lane]);
        float4 a1 = __ldcs(&xr0[lane + 32]);

        float s0 = a0.x * b0.x + a0.y * b0.y + a0.z * b0.z + a0.w * b0.w
                 + a1.x * b1.x + a1.y * b1.y + a1.z * b1.z + a1.w * b1.w;

        float s1 = 0.0f;
        if (r1 < N) {
            const float4* xr1 = reinterpret_cast<const float4*>(x + (size_t)r1 * C);
            float4 c0 = __ldcs(&xr1[lane]);
            float4 c1 = __ldcs(&xr1[lane + 32]);
            s1 = c0.x * b0.x + c0.y * b0.y + c0.z * b0.z + c0.w * b0.w
               + c1.x * b1.x + c1.y * b1.y + c1.z * b1.z + c1.w * b1.w;
        }

        #pragma unroll
        for (int off = 16; off > 0; off >>= 1) {
            s0 += __shfl_xor_sync(0xffffffffu, s0, off);
            s1 += __shfl_xor_sync(0xffffffffu, s1, off);
        }

        if (lane == 0) {
            g_h[r0] = s0;
            if (r1 < N) g_h[r1] = s1;
        }
    }

    int stride = gridDim.x * blockDim.x;
    for (int i = tid; i < E; i += stride)
        atomicAdd(&g_deg8[(unsigned)dst[i] * PAD], 1.0f);
}

// ---------------------------------------------------------------------------
// K3 (PDL secondary): dinv = rsqrt(deg+1); ph = fp16(dinv*h), packed store.
// ---------------------------------------------------------------------------
__global__ void k3_norm(int N) {
    cudaGridDependencySynchronize();   // wait for k1's atomics to be visible

    int t = blockIdx.x * blockDim.x + threadIdx.x;
    int i0 = t * 2, i1 = i0 + 1;
    if (i0 < N) {
        float d0 = g_deg8[(unsigned)i0 * PAD];
        float d1 = (i1 < N) ? g_deg8[(unsigned)i1 * PAD] : 0.0f;
        float h0 = g_h[i0];
        float h1 = (i1 < N) ? g_h[i1] : 0.0f;

        g_deg8[(unsigned)i0 * PAD] = 0.0f;
        float v0 = rsqrtf(d0 + 1.0f);
        float v1 = rsqrtf(d1 + 1.0f);
        g_dinv[i0] = v0;

        if (i1 < N) {
            g_deg8[(unsigned)i1 * PAD] = 0.0f;
            g_dinv[i1] = v1;
            *reinterpret_cast<__half2*>(&g_ph[i0]) =
                __floats2half2_rn(v0 * h0, v1 * h1);
        } else {
            g_ph[i0] = __float2half_rn(v0 * h0);
        }
    }
}

// ---------------------------------------------------------------------------
// K4 (PDL secondary): persistent, one block/SM. Stage fp16 p-vector into SMEM
// (200KB), then 2 edges/thread gathering from SMEM; atomics to padded bins.
// ---------------------------------------------------------------------------
__global__ void __launch_bounds__(1024, 1)
k4_scatter_smem(const int* __restrict__ src,
                const int* __restrict__ dst, int N, int E) {
    extern __shared__ __half sph[];

    cudaGridDependencySynchronize();   // wait for k3's ph writes

    int n16 = (N * 2 + 15) / 16;   // uint4 count (MAXN padding: safe over-read)
    const uint4* gp4 = reinterpret_cast<const uint4*>(g_ph);
    uint4* sp4 = reinterpret_cast<uint4*>(sph);
    for (int i = threadIdx.x; i < n16; i += blockDim.x)
        sp4[i] = gp4[i];
    __syncthreads();

    int tid = blockIdx.x * blockDim.x + threadIdx.x;
    int stride = gridDim.x * blockDim.x;

    int E2 = E >> 1;
    const int2* src2 = reinterpret_cast<const int2*>(src);
    const int2* dst2 = reinterpret_cast<const int2*>(dst);
    for (int i = tid; i < E2; i += stride) {
        int2 s = src2[i];
        int2 d = dst2[i];
        float p0 = __half2float(sph[s.x]);
        float p1 = __half2float(sph[s.y]);
        atomicAdd(&g_acc8[(unsigned)d.x * PAD], p0);
        atomicAdd(&g_acc8[(unsigned)d.y * PAD], p1);
    }
    if ((E & 1) && tid == 0) {
        int t = E - 1;
        atomicAdd(&g_acc8[(unsigned)dst[t] * PAD], __half2float(sph[src[t]]));
    }
}

// fallback if SMEM staging impossible
__global__ void k4_scatter_fallback(const int* __restrict__ src,
                                    const int* __restrict__ dst, int E) {
    int i = blockIdx.x * blockDim.x + threadIdx.x;
    int stride = gridDim.x * blockDim.x;
    for (; i < E; i += stride)
        atomicAdd(&g_acc8[(unsigned)dst[i] * PAD], __half2float(g_ph[src[i]]));
}

// ---------------------------------------------------------------------------
// K5 (PDL secondary): out = softplus(dinv*(acc + dinv*h) + b); zero acc bins.
// ---------------------------------------------------------------------------
__global__ void k5_epilogue(float* __restrict__ out,
                            const float* __restrict__ b, int N) {
    cudaGridDependencySynchronize();   // wait for k4's atomics

    int t = blockIdx.x * blockDim.x + threadIdx.x;
    int i0 = t * 2, i1 = i0 + 1;
    if (i0 < N) {
        float bb = b[0];
        float a0 = g_acc8[(unsigned)i0 * PAD];
        float a1 = (i1 < N) ? g_acc8[(unsigned)i1 * PAD] : 0.0f;
        float h0 = g_h[i0];
        float h1 = (i1 < N) ? g_h[i1] : 0.0f;
        float q0 = g_dinv[i0];
        float q1 = (i1 < N) ? g_dinv[i1] : 0.0f;

        g_acc8[(unsigned)i0 * PAD] = 0.0f;
        float v0 = q0 * (a0 + q0 * h0) + bb;
        out[i0] = fmaxf(v0, 0.0f) + log1pf(expf(-fabsf(v0)));

        if (i1 < N) {
            g_acc8[(unsigned)i1 * PAD] = 0.0f;
            float v1 = q1 * (a1 + q1 * h1) + bb;
            out[i1] = fmaxf(v1, 0.0f) + log1pf(expf(-fabsf(v1)));
        }
    }
}

extern "C" void kernel_launch(void* const* d_in, const int* in_sizes, int n_in,
                              void* d_out, int out_size) {
    const float* x   = (const float*)d_in[0];
    const int*   ei  = (const int*)d_in[1];   // [2, E], int32
    const float* W   = (const float*)d_in[2];
    const float* b   = (const float*)d_in[3];
    float*       out = (float*)d_out;

    int C = in_sizes[2];            // 256
    int N = in_sizes[0] / C;        // 100000
    int E = in_sizes[1] / 2;        // 3200000

    const int* src = ei;
    const int* dst = ei + E;

    // K1: normal launch (no predecessor)
    {
        int rows_per_block = 32;
        int blocks = (N + rows_per_block - 1) / rows_per_block;
        k1_fused<<<blocks, 512>>>(x, W, dst, N, C, E);
    }

    // PDL attribute shared by the dependent launches
    cudaLaunchAttribute pdl[1];
    pdl[0].id = cudaLaunchAttributeProgrammaticStreamSerialization;
    pdl[0].val.programmaticStreamSerializationAllowed = 1;

    // K3: PDL secondary
    {
        int threads = 256;
        int work = (N + 1) / 2;
        int blocks = (work + threads - 1) / threads;
        cudaLaunchConfig_t cfg = {};
        cfg.gridDim = dim3(blocks); cfg.blockDim = dim3(threads);
        cfg.dynamicSmemBytes = 0; cfg.stream = 0;
        cfg.attrs = pdl; cfg.numAttrs = 1;
        cudaLaunchKernelEx(&cfg, k3_norm, N);
    }
    // K4: PDL secondary, persistent SMEM-staged scatter
    {
        int sm_count = 148;
        cudaDeviceGetAttribute(&sm_count, cudaDevAttrMultiProcessorCount, 0);
        size_t smem_bytes = ((size_t)N * 2 + 15) & ~(size_t)15;
        static int attr_set = 0;
        if (!attr_set) {
            cudaFuncSetAttribute(k4_scatter_smem,
                                 cudaFuncAttributeMaxDynamicSharedMemorySize,
                                 227 * 1024);
            attr_set = 1;
        }
        bool aligned = ((((size_t)src) & 7) == 0) && ((((size_t)dst) & 7) == 0);
        if (smem_bytes <= 227 * 1024 && aligned) {
            cudaLaunchConfig_t cfg = {};
            cfg.gridDim = dim3(sm_count); cfg.blockDim = dim3(1024);
            cfg.dynamicSmemBytes = smem_bytes; cfg.stream = 0;
            cfg.attrs = pdl; cfg.numAttrs = 1;
            cudaLaunchKernelEx(&cfg, k4_scatter_smem, src, dst, N, E);
        } else {
            int threads = 256;
            int blocks = (E + threads - 1) / threads;
            if (blocks > 65535) blocks = 65535;
            k4_scatter_fallback<<<blocks, threads>>>(src, dst, E);
        }
    }
    // K5: PDL secondary
    {
        int threads = 256;
        int work = (N + 1) / 2;
        int blocks = (work + threads - 1) / threads;
        cudaLaunchConfig_t cfg = {};
        cfg.gridDim = dim3(blocks); cfg.blockDim = dim3(threads);
        cfg.dynamicSmemBytes = 0; cfg.stream = 0;
        cfg.attrs = pdl; cfg.numAttrs = 1;
        cudaLaunchKernelEx(&cfg, k5_epilogue, out, b, N);
    }
}

// round 16
// speedup vs baseline: 1.2519x; 1.2519x over previous
#include <cuda_runtime.h>
#include <cuda_fp16.h>
#include <stdint.h>
#include <math.h>

#define MAXN 131072
#define PAD  8   // one slot per 32B L2 sector for atomic targets

__device__ float  g_h[MAXN];            // x @ W                  [N]
__device__ float  g_dinv[MAXN];         // rsqrt(deg+1)           [N]
__device__ __half g_ph[MAXN];           // fp16 p = dinv*h        [N]
__device__ int    g_degi[MAXN * PAD];   // sector-padded degree (int RED) zeroed after use
__device__ float  g_acc8[MAXN * PAD];   // sector-padded scatter  (zeroed after use)

// ---------------------------------------------------------------------------
// K1 (fused): per-warp row dot products, 2 rows/warp (ILP), streaming loads
// + grid-stride degree histogram with INT32 atomics into padded bins.
// ---------------------------------------------------------------------------
__global__ void k1_fused(const float* __restrict__ x,
                         const float* __restrict__ W,
                         const int*   __restrict__ dst,
                         int N, int C, int E) {
    int tid  = blockIdx.x * blockDim.x + threadIdx.x;
    int warp = tid >> 5;
    int lane = tid & 31;

    int r0 = warp * 2;
    int r1 = r0 + 1;

    if (r0 < N) {
        const float4* w4 = reinterpret_cast<const float4*>(W);
        float4 b0 = __ldg(&w4[lane]);
        float4 b1 = __ldg(&w4[lane + 32]);

        const float4* xr0 = reinterpret_cast<const float4*>(x + (size_t)r0 * C);
        float4 a0 = __ldcs(&xr0[lane]);
        float4 a1 = __ldcs(&xr0[lane + 32]);

        float s0 = a0.x * b0.x + a0.y * b0.y + a0.z * b0.z + a0.w * b0.w
                 + a1.x * b1.x + a1.y * b1.y + a1.z * b1.z + a1.w * b1.w;

        float s1 = 0.0f;
        if (r1 < N) {
            const float4* xr1 = reinterpret_cast<const float4*>(x + (size_t)r1 * C);
            float4 c0 = __ldcs(&xr1[lane]);
            float4 c1 = __ldcs(&xr1[lane + 32]);
            s1 = c0.x * b0.x + c0.y * b0.y + c0.z * b0.z + c0.w * b0.w
               + c1.x * b1.x + c1.y * b1.y + c1.z * b1.z + c1.w * b1.w;
        }

        #pragma unroll
        for (int off = 16; off > 0; off >>= 1) {
            s0 += __shfl_xor_sync(0xffffffffu, s0, off);
            s1 += __shfl_xor_sync(0xffffffffu, s1, off);
        }

        if (lane == 0) {
            g_h[r0] = s0;
            if (r1 < N) g_h[r1] = s1;
        }
    }

    // degree histogram: INT32 RED.ADD (testing LTS int-vs-float RED rate)
    int stride = gridDim.x * blockDim.x;
    for (int i = tid; i < E; i += stride)
        atomicAdd(&g_degi[(unsigned)dst[i] * PAD], 1);
}

// ---------------------------------------------------------------------------
// K3: dinv = rsqrt(deg+1); ph = fp16(dinv*h); re-zero deg bins. 2 nodes/thread.
// ---------------------------------------------------------------------------
__global__ void k3_norm(int N) {
    int t = blockIdx.x * blockDim.x + threadIdx.x;
    int i0 = t * 2, i1 = i0 + 1;
    if (i0 < N) {
        int   d0 = g_degi[(unsigned)i0 * PAD];
        int   d1 = (i1 < N) ? g_degi[(unsigned)i1 * PAD] : 0;
        float h0 = g_h[i0];
        float h1 = (i1 < N) ? g_h[i1] : 0.0f;

        g_degi[(unsigned)i0 * PAD] = 0;
        float v0 = rsqrtf((float)d0 + 1.0f);
        g_dinv[i0] = v0;
        g_ph[i0] = __float2half_rn(v0 * h0);

        if (i1 < N) {
            g_degi[(unsigned)i1 * PAD] = 0;
            float v1 = rsqrtf((float)d1 + 1.0f);
            g_dinv[i1] = v1;
            g_ph[i1] = __float2half_rn(v1 * h1);
        }
    }
}

// ---------------------------------------------------------------------------
// K4: persistent, one block/SM. Stage fp16 p-vector into SMEM (200KB), then
// grid-stride edges gathering from SMEM; fp32 atomics to padded L2 bins.
// At the LTS RED-throughput ceiling — R10 exact.
// ---------------------------------------------------------------------------
__global__ void __launch_bounds__(1024, 1)
k4_scatter_smem(const int* __restrict__ src,
                const int* __restrict__ dst, int N, int E) {
    extern __shared__ __half sph[];

    int n16 = (N * 2 + 15) / 16;   // uint4 count (MAXN padding: safe over-read)
    const uint4* gp4 = reinterpret_cast<const uint4*>(g_ph);
    uint4* sp4 = reinterpret_cast<uint4*>(sph);
    for (int i = threadIdx.x; i < n16; i += blockDim.x)
        sp4[i] = gp4[i];
    __syncthreads();

    int tid = blockIdx.x * blockDim.x + threadIdx.x;
    int stride = gridDim.x * blockDim.x;
    for (int i = tid; i < E; i += stride) {
        int s = src[i];
        int d = dst[i];
        atomicAdd(&g_acc8[(unsigned)d * PAD], __half2float(sph[s]));
    }
}

// fallback if N too large for SMEM staging
__global__ void k4_scatter_fallback(const int* __restrict__ src,
                                    const int* __restrict__ dst, int E) {
    int i = blockIdx.x * blockDim.x + threadIdx.x;
    int stride = gridDim.x * blockDim.x;
    for (; i < E; i += stride)
        atomicAdd(&g_acc8[(unsigned)dst[i] * PAD], __half2float(g_ph[src[i]]));
}

// ---------------------------------------------------------------------------
// K5: out = softplus(dinv*(acc + dinv*h) + b); re-zero acc bins. 2/thread.
// ---------------------------------------------------------------------------
__global__ void k5_epilogue(float* __restrict__ out,
                            const float* __restrict__ b, int N) {
    int t = blockIdx.x * blockDim.x + threadIdx.x;
    int i0 = t * 2, i1 = i0 + 1;
    if (i0 < N) {
        float bb = b[0];
        float a0 = g_acc8[(unsigned)i0 * PAD];
        float a1 = (i1 < N) ? g_acc8[(unsigned)i1 * PAD] : 0.0f;
        float h0 = g_h[i0];
        float h1 = (i1 < N) ? g_h[i1] : 0.0f;
        float q0 = g_dinv[i0];
        float q1 = (i1 < N) ? g_dinv[i1] : 0.0f;

        g_acc8[(unsigned)i0 * PAD] = 0.0f;
        float v0 = q0 * (a0 + q0 * h0) + bb;
        out[i0] = fmaxf(v0, 0.0f) + log1pf(expf(-fabsf(v0)));

        if (i1 < N) {
            g_acc8[(unsigned)i1 * PAD] = 0.0f;
            float v1 = q1 * (a1 + q1 * h1) + bb;
            out[i1] = fmaxf(v1, 0.0f) + log1pf(expf(-fabsf(v1)));
        }
    }
}

extern "C" void kernel_launch(void* const* d_in, const int* in_sizes, int n_in,
                              void* d_out, int out_size) {
    const float* x   = (const float*)d_in[0];
    const int*   ei  = (const int*)d_in[1];   // [2, E], int32
    const float* W   = (const float*)d_in[2];
    const float* b   = (const float*)d_in[3];
    float*       out = (float*)d_out;

    int C = in_sizes[2];            // 256
    int N = in_sizes[0] / C;        // 100000
    int E = in_sizes[1] / 2;        // 3200000

    const int* src = ei;
    const int* dst = ei + E;

    // K1 fused: 512 threads = 16 warps = 32 rows/block (2 rows/warp)
    {
        int rows_per_block = 32;
        int blocks = (N + rows_per_block - 1) / rows_per_block;
        k1_fused<<<blocks, 512>>>(x, W, dst, N, C, E);
    }
    // K3: 2 nodes/thread
    {
        int threads = 256;
        int work = (N + 1) / 2;
        int blocks = (work + threads - 1) / threads;
        k3_norm<<<blocks, threads>>>(N);
    }
    // K4: persistent SMEM-staged scatter (one block per SM)
    {
        int sm_count = 148;
        cudaDeviceGetAttribute(&sm_count, cudaDevAttrMultiProcessorCount, 0);
        size_t smem_bytes = ((size_t)N * 2 + 15) & ~(size_t)15;
        static int attr_set = 0;
        if (!attr_set) {
            cudaFuncSetAttribute(k4_scatter_smem,
                                 cudaFuncAttributeMaxDynamicSharedMemorySize,
                                 227 * 1024);
            attr_set = 1;
        }
        if (smem_bytes <= 227 * 1024) {
            k4_scatter_smem<<<sm_count, 1024, smem_bytes>>>(src, dst, N, E);
        } else {
            int threads = 256;
            int blocks = (E + threads - 1) / threads;
            if (blocks > 65535) blocks = 65535;
            k4_scatter_fallback<<<blocks, threads>>>(src, dst, E);
        }
    }
    // K5: 2 nodes/thread
    {
        int threads = 256;
        int work = (N + 1) / 2;
        int blocks = (work + threads - 1) / threads;
        k5_epilogue<<<blocks, threads>>>(out, b, N);
    }
}

// round 17
// speedup vs baseline: 1.2547x; 1.0023x over previous
#include <cuda_runtime.h>
#include <cuda_fp16.h>
#include <stdint.h>
#include <math.h>

#define MAXN 131072
#define PAD  8   // one slot per 32B L2 sector for atomic targets

__device__ float  g_h[MAXN];            // x @ W                  [N]
__device__ float  g_dinv[MAXN];         // rsqrt(deg+1)           [N]
__device__ __half g_ph[MAXN];           // fp16 p = dinv*h        [N]
__device__ int    g_degi[MAXN * PAD];   // sector-padded degree (int RED), zeroed after use
__device__ float  g_acc8[MAXN * PAD];   // sector-padded scatter  (zeroed after use)

// ---------------------------------------------------------------------------
// K1 (fused): per-warp row dot products, 2 rows/warp (ILP), streaming loads
// + grid-stride degree histogram (int2 edge loads, INT32 REDs, padded bins).
// ---------------------------------------------------------------------------
__global__ void k1_fused(const float* __restrict__ x,
                         const float* __restrict__ W,
                         const int*   __restrict__ dst,
                         int N, int C, int E) {
    int tid  = blockIdx.x * blockDim.x + threadIdx.x;
    int warp = tid >> 5;
    int lane = tid & 31;

    int r0 = warp * 2;
    int r1 = r0 + 1;

    if (r0 < N) {
        const float4* w4 = reinterpret_cast<const float4*>(W);
        float4 b0 = __ldg(&w4[lane]);
        float4 b1 = __ldg(&w4[lane + 32]);

        const float4* xr0 = reinterpret_cast<const float4*>(x + (size_t)r0 * C);
        float4 a0 = __ldcs(&xr0[lane]);
        float4 a1 = __ldcs(&xr0[lane + 32]);

        float s0 = a0.x * b0.x + a0.y * b0.y + a0.z * b0.z + a0.w * b0.w
                 + a1.x * b1.x + a1.y * b1.y + a1.z * b1.z + a1.w * b1.w;

        float s1 = 0.0f;
        if (r1 < N) {
            const float4* xr1 = reinterpret_cast<const float4*>(x + (size_t)r1 * C);
            float4 c0 = __ldcs(&xr1[lane]);
            float4 c1 = __ldcs(&xr1[lane + 32]);
            s1 = c0.x * b0.x + c0.y * b0.y + c0.z * b0.z + c0.w * b0.w
               + c1.x * b1.x + c1.y * b1.y + c1.z * b1.z + c1.w * b1.w;
        }

        #pragma unroll
        for (int off = 16; off > 0; off >>= 1) {
            s0 += __shfl_xor_sync(0xffffffffu, s0, off);
            s1 += __shfl_xor_sync(0xffffffffu, s1, off);
        }

        if (lane == 0) {
            g_h[r0] = s0;
            if (r1 < N) g_h[r1] = s1;
        }
    }

    // degree histogram: 2 edges/iter via int2 loads, INT32 RED.ADD
    int stride = gridDim.x * blockDim.x;
    int E2 = E >> 1;
    const int2* dst2 = reinterpret_cast<const int2*>(dst);
    for (int i = tid; i < E2; i += stride) {
        int2 d = dst2[i];
        atomicAdd(&g_degi[(unsigned)d.x * PAD], 1);
        atomicAdd(&g_degi[(unsigned)d.y * PAD], 1);
    }
    if ((E & 1) && tid == 0)
        atomicAdd(&g_degi[(unsigned)dst[E - 1] * PAD], 1);
}

// ---------------------------------------------------------------------------
// K3: dinv = rsqrt(deg+1); ph = fp16(dinv*h) packed half2 store; zero deg bins.
// 2 adjacent nodes/thread.
// ---------------------------------------------------------------------------
__global__ void k3_norm(int N) {
    int t = blockIdx.x * blockDim.x + threadIdx.x;
    int i0 = t * 2, i1 = i0 + 1;
    if (i0 < N) {
        int   d0 = g_degi[(unsigned)i0 * PAD];
        int   d1 = (i1 < N) ? g_degi[(unsigned)i1 * PAD] : 0;
        float h0 = g_h[i0];
        float h1 = (i1 < N) ? g_h[i1] : 0.0f;

        g_degi[(unsigned)i0 * PAD] = 0;
        float v0 = rsqrtf((float)d0 + 1.0f);
        float v1 = rsqrtf((float)d1 + 1.0f);
        g_dinv[i0] = v0;

        if (i1 < N) {
            g_degi[(unsigned)i1 * PAD] = 0;
            g_dinv[i1] = v1;
            // i0 even -> 4B-aligned packed store
            *reinterpret_cast<__half2*>(&g_ph[i0]) =
                __floats2half2_rn(v0 * h0, v1 * h1);
        } else {
            g_ph[i0] = __float2half_rn(v0 * h0);
        }
    }
}

// ---------------------------------------------------------------------------
// K4: persistent, one block/SM. Stage fp16 p-vector into SMEM (200KB), then
// grid-stride edges gathering from SMEM; fp32 atomics to padded L2 bins.
// At the chip REDG-issue floor — measured-best shape.
// ---------------------------------------------------------------------------
__global__ void __launch_bounds__(1024, 1)
k4_scatter_smem(const int* __restrict__ src,
                const int* __restrict__ dst, int N, int E) {
    extern __shared__ __half sph[];

    int n16 = (N * 2 + 15) / 16;   // uint4 count (MAXN padding: safe over-read)
    const uint4* gp4 = reinterpret_cast<const uint4*>(g_ph);
    uint4* sp4 = reinterpret_cast<uint4*>(sph);
    for (int i = threadIdx.x; i < n16; i += blockDim.x)
        sp4[i] = gp4[i];
    __syncthreads();

    int tid = blockIdx.x * blockDim.x + threadIdx.x;
    int stride = gridDim.x * blockDim.x;
    for (int i = tid; i < E; i += stride) {
        int s = src[i];
        int d = dst[i];
        atomicAdd(&g_acc8[(unsigned)d * PAD], __half2float(sph[s]));
    }
}

// fallback if N too large for SMEM staging
__global__ void k4_scatter_fallback(const int* __restrict__ src,
                                    const int* __restrict__ dst, int E) {
    int i = blockIdx.x * blockDim.x + threadIdx.x;
    int stride = gridDim.x * blockDim.x;
    for (; i < E; i += stride)
        atomicAdd(&g_acc8[(unsigned)dst[i] * PAD], __half2float(g_ph[src[i]]));
}

// ---------------------------------------------------------------------------
// K5: out = softplus(dinv*(acc + dinv*h) + b); zero acc bins. 2 nodes/thread.
// ---------------------------------------------------------------------------
__global__ void k5_epilogue(float* __restrict__ out,
                            const float* __restrict__ b, int N) {
    int t = blockIdx.x * blockDim.x + threadIdx.x;
    int i0 = t * 2, i1 = i0 + 1;
    if (i0 < N) {
        float bb = __ldg(b);
        float a0 = g_acc8[(unsigned)i0 * PAD];
        float a1 = (i1 < N) ? g_acc8[(unsigned)i1 * PAD] : 0.0f;
        float h0 = g_h[i0];
        float h1 = (i1 < N) ? g_h[i1] : 0.0f;
        float q0 = g_dinv[i0];
        float q1 = (i1 < N) ? g_dinv[i1] : 0.0f;

        g_acc8[(unsigned)i0 * PAD] = 0.0f;
        float v0 = q0 * (a0 + q0 * h0) + bb;
        out[i0] = fmaxf(v0, 0.0f) + log1pf(expf(-fabsf(v0)));

        if (i1 < N) {
            g_acc8[(unsigned)i1 * PAD] = 0.0f;
            float v1 = q1 * (a1 + q1 * h1) + bb;
            out[i1] = fmaxf(v1, 0.0f) + log1pf(expf(-fabsf(v1)));
        }
    }
}

extern "C" void kernel_launch(void* const* d_in, const int* in_sizes, int n_in,
                              void* d_out, int out_size) {
    const float* x   = (const float*)d_in[0];
    const int*   ei  = (const int*)d_in[1];   // [2, E], int32
    const float* W   = (const float*)d_in[2];
    const float* b   = (const float*)d_in[3];
    float*       out = (float*)d_out;

    int C = in_sizes[2];            // 256
    int N = in_sizes[0] / C;        // 100000
    int E = in_sizes[1] / 2;        // 3200000

    const int* src = ei;
    const int* dst = ei + E;

    // K1 fused: 512 threads = 16 warps = 32 rows/block (2 rows/warp)
    {
        int rows_per_block = 32;
        int blocks = (N + rows_per_block - 1) / rows_per_block;
        k1_fused<<<blocks, 512>>>(x, W, dst, N, C, E);
    }
    // K3: 2 nodes/thread
    {
        int threads = 256;
        int work = (N + 1) / 2;
        int blocks = (work + threads - 1) / threads;
        k3_norm<<<blocks, threads>>>(N);
    }
    // K4: persistent SMEM-staged scatter (one block per SM)
    {
        int sm_count = 148;
        cudaDeviceGetAttribute(&sm_count, cudaDevAttrMultiProcessorCount, 0);
        size_t smem_bytes = ((size_t)N * 2 + 15) & ~(size_t)15;
        static int attr_set = 0;
        if (!attr_set) {
            cudaFuncSetAttribute(k4_scatter_smem,
                                 cudaFuncAttributeMaxDynamicSharedMemorySize,
                                 227 * 1024);
            attr_set = 1;
        }
        if (smem_bytes <= 227 * 1024) {
            k4_scatter_smem<<<sm_count, 1024, smem_bytes>>>(src, dst, N, E);
        } else {
            int threads = 256;
            int blocks = (E + threads - 1) / threads;
            if (blocks > 65535) blocks = 65535;
            k4_scatter_fallback<<<blocks, threads>>>(src, dst, E);
        }
    }
    // K5: 2 nodes/thread
    {
        int threads = 256;
        int work = (N + 1) / 2;
        int blocks = (work + threads - 1) / threads;
        k5_epilogue<<<blocks, threads>>>(out, b, N);
    }
}